// round 15
// baseline (speedup 1.0000x reference)
#include <cuda_runtime.h>
#include <cuda_fp16.h>
#include <math.h>

#define NN 15000
#define NE 30000
#define NG 600
#define NS 6000
#define NJ 3000
#define STEM_OFF 1200
#define JB_OFF 631200

// ---------------- persistent device scratch ----------------
__device__ __half g_We_h[(size_t)NE * 4096]; // [E][64][64] edge weight matrices, fp16 (245.8 MB)
__device__ float g_h1[NE * 64];
__device__ float g_out[NN * 64];
__device__ float g_h[NN * 64];
__device__ float g_agg[NN * 64];
__device__ float g_deg[NN];
__device__ float g_invdeg[NN];
__device__ float g_wt8[64 * 64 * 8];        // interleaved transposed GRU weights
__device__ float g_s1T[64 * 64];
__device__ float g_s2T[64 * 105];
__device__ float g_j1T[64 * 64];
__device__ float g_q[64];
__device__ float g_e[NN];
__device__ float g_aun[NN];
__device__ unsigned g_emax[NG];
__device__ float g_asum[NG];
__device__ float g_rpool[NG * 64];
__device__ float g_jb[NS];

__device__ __forceinline__ float lrelu(float v) { return v > 0.f ? v : 0.01f * v; }
__device__ __forceinline__ float sigm(float v) { return 1.f / (1.f + expf(-v)); }
__device__ __forceinline__ unsigned fkey(float f) {
    unsigned u = __float_as_uint(f);
    return (u & 0x80000000u) ? ~u : (u | 0x80000000u);
}
__device__ __forceinline__ float funkey(unsigned k) {
    return (k & 0x80000000u) ? __uint_as_float(k ^ 0x80000000u) : __uint_as_float(~k);
}

// packed f32x2 helpers (Blackwell FFMA2 path)
__device__ __forceinline__ unsigned long long dup2(float x) {
    unsigned long long r;
    asm("mov.b64 %0, {%1, %1};" : "=l"(r) : "r"(__float_as_uint(x)));
    return r;
}
__device__ __forceinline__ void fma2(unsigned long long& d, unsigned long long a,
                                     unsigned long long b) {
    asm("fma.rn.f32x2 %0, %1, %2, %0;" : "+l"(d) : "l"(a), "l"(b));
}
__device__ __forceinline__ float2 unpack2(unsigned long long v) {
    float2 f;
    asm("mov.b64 {%0, %1}, %2;" : "=f"(f.x), "=f"(f.y) : "l"(v));
    return f;
}

// ---------------- init: out = h = lrelu(x @ lin0_w^T + b) ----------------
__global__ void k_lin0(const float* __restrict__ x, const float* __restrict__ w,
                       const float* __restrict__ b) {
    int idx = blockIdx.x * blockDim.x + threadIdx.x;
    if (idx >= NN * 64) return;
    int n = idx >> 6, j = idx & 63;
    float acc = b[j];
#pragma unroll
    for (int k = 0; k < 14; k++) acc = fmaf(x[n * 14 + k], w[j * 14 + k], acc);
    float v = lrelu(acc);
    g_out[idx] = v;
    g_h[idx] = v;
}

__global__ void k_deg(const int* __restrict__ ei) {
    int e = blockIdx.x * blockDim.x + threadIdx.x;
    if (e >= NE) return;
    atomicAdd(&g_deg[ei[NE + e]], 1.0f);
}

__global__ void k_invdeg() {
    int n = blockIdx.x * blockDim.x + threadIdx.x;
    if (n >= NN) return;
    g_invdeg[n] = 1.0f / fmaxf(g_deg[n], 1.0f);
}

// ---------------- edge hidden: h1 = lrelu(edge_attr @ en1^T + b) ----------------
__global__ void k_h1e(const float* __restrict__ ea, const float* __restrict__ w,
                      const float* __restrict__ b) {
    int idx = blockIdx.x * blockDim.x + threadIdx.x;
    if (idx >= NE * 64) return;
    int e = idx >> 6, j = idx & 63;
    float acc = b[j];
#pragma unroll
    for (int k = 0; k < 4; k++) acc = fmaf(ea[e * 4 + k], w[j * 4 + k], acc);
    g_h1[idx] = lrelu(acc);
}

// ---------------- We GEMM: [30000,64] @ [64,4096] + bias -> fp16 store ----------------
// tile 128(e) x 128(j), BK=32, 8x8 per thread via packed f32x2
__global__ void __launch_bounds__(256, 2) k_We(const float* __restrict__ w,
                                               const float* __restrict__ bias) {
    __shared__ float As[32][128];  // [k][e]
    __shared__ float Bs[32][128];  // [k][j]
    int t = threadIdx.x;
    int j0 = blockIdx.x * 128;
    int e0 = blockIdx.y * 128;
    int tx = t & 15, ty = t >> 4;
    unsigned long long acc2[8][4];
#pragma unroll
    for (int r = 0; r < 8; r++)
#pragma unroll
        for (int c = 0; c < 4; c++) acc2[r][c] = 0ull;

    for (int k0 = 0; k0 < 64; k0 += 32) {
#pragma unroll
        for (int p = 0; p < 4; p++) {
            int idx = p * 256 + t;
            int e = idx & 127;
            int kq = idx >> 7;
            float4 v = make_float4(0.f, 0.f, 0.f, 0.f);
            int ge = e0 + e;
            if (ge < NE) v = *(const float4*)(g_h1 + ge * 64 + k0 + kq * 4);
            As[kq * 4 + 0][e] = v.x; As[kq * 4 + 1][e] = v.y;
            As[kq * 4 + 2][e] = v.z; As[kq * 4 + 3][e] = v.w;
        }
#pragma unroll
        for (int p = 0; p < 4; p++) {
            int idx = p * 256 + t;
            int j = idx & 127;
            int kq = idx >> 7;
            float4 v = *(const float4*)(w + (j0 + j) * 64 + k0 + kq * 4);
            Bs[kq * 4 + 0][j] = v.x; Bs[kq * 4 + 1][j] = v.y;
            Bs[kq * 4 + 2][j] = v.z; Bs[kq * 4 + 3][j] = v.w;
        }
        __syncthreads();
#pragma unroll
        for (int k = 0; k < 32; k++) {
            float4 a0 = *(const float4*)(&As[k][ty * 8]);
            float4 a1 = *(const float4*)(&As[k][ty * 8 + 4]);
            const double* Bd = (const double*)(&Bs[k][tx * 8]);
            unsigned long long b2[4];
            b2[0] = __double_as_longlong(Bd[0]);
            b2[1] = __double_as_longlong(Bd[1]);
            b2[2] = __double_as_longlong(Bd[2]);
            b2[3] = __double_as_longlong(Bd[3]);
            unsigned long long av[8];
            av[0] = dup2(a0.x); av[1] = dup2(a0.y); av[2] = dup2(a0.z); av[3] = dup2(a0.w);
            av[4] = dup2(a1.x); av[5] = dup2(a1.y); av[6] = dup2(a1.z); av[7] = dup2(a1.w);
#pragma unroll
            for (int r = 0; r < 8; r++)
#pragma unroll
                for (int c = 0; c < 4; c++) fma2(acc2[r][c], av[r], b2[c]);
        }
        __syncthreads();
    }
    float bj[8];
    *(float4*)(&bj[0]) = *(const float4*)(bias + j0 + tx * 8);
    *(float4*)(&bj[4]) = *(const float4*)(bias + j0 + tx * 8 + 4);
#pragma unroll
    for (int r = 0; r < 8; r++) {
        int ge = e0 + ty * 8 + r;
        if (ge >= NE) continue;
        float2 p0 = unpack2(acc2[r][0]);
        float2 p1 = unpack2(acc2[r][1]);
        float2 p2 = unpack2(acc2[r][2]);
        float2 p3 = unpack2(acc2[r][3]);
        __half2 h0 = __floats2half2_rn(p0.x + bj[0], p0.y + bj[1]);
        __half2 h1 = __floats2half2_rn(p1.x + bj[2], p1.y + bj[3]);
        __half2 h2 = __floats2half2_rn(p2.x + bj[4], p2.y + bj[5]);
        __half2 h3 = __floats2half2_rn(p3.x + bj[6], p3.y + bj[7]);
        uint4 packed;
        packed.x = *(unsigned*)&h0;
        packed.y = *(unsigned*)&h1;
        packed.z = *(unsigned*)&h2;
        packed.w = *(unsigned*)&h3;
        *(uint4*)(g_We_h + (size_t)ge * 4096 + j0 + tx * 8) = packed;
    }
}

// ---------------- weight preprocessing ----------------
__global__ void k_prep_wt8(const float* __restrict__ wih, const float* __restrict__ whh) {
    int idx = blockIdx.x * blockDim.x + threadIdx.x;
    if (idx >= 64 * 64) return;
    int k = idx >> 6, j = idx & 63;
    float* w8 = g_wt8 + idx * 8;
    w8[0] = wih[j * 64 + k];
    w8[1] = wih[(64 + j) * 64 + k];
    w8[2] = wih[(128 + j) * 64 + k];
    w8[3] = whh[j * 64 + k];
    w8[4] = whh[(64 + j) * 64 + k];
    w8[5] = whh[(128 + j) * 64 + k];
    w8[6] = 0.f;
    w8[7] = 0.f;
}

__global__ void k_prep_misc(const float* __restrict__ s1w, const float* __restrict__ s2w,
                            const float* __restrict__ j1w) {
    int idx = blockIdx.x * blockDim.x + threadIdx.x;
    if (idx < 64 * 64) {
        int k = idx >> 6, j = idx & 63;
        g_s1T[idx] = s1w[j * 64 + k];
        g_j1T[idx] = j1w[j * 64 + k];
    }
    if (idx < 64 * 105) {
        int j = idx / 105, p = idx % 105;
        g_s2T[idx] = s2w[p * 64 + j];
    }
}

// ---------------- message: warp per edge, fp16 We stream, scatter to agg ----------------
__global__ void k_msg(const int* __restrict__ ei) {
    int gw = (blockIdx.x * blockDim.x + threadIdx.x) >> 5;
    int lane = threadIdx.x & 31;
    if (gw >= NE) return;
    int s = ei[gw];
    int d = ei[NE + gw];
    float a0 = g_out[s * 64 + lane];
    float a1 = g_out[s * 64 + 32 + lane];
    const __half2* W = (const __half2*)(g_We_h + (size_t)gw * 4096);
    float acc0 = 0.f, acc1 = 0.f;
#pragma unroll
    for (int i = 0; i < 32; i++) {
        float ai = __shfl_sync(0xffffffffu, a0, i);
        float2 wv = __half22float2(W[i * 32 + lane]);
        acc0 = fmaf(ai, wv.x, acc0);
        acc1 = fmaf(ai, wv.y, acc1);
    }
#pragma unroll
    for (int i = 0; i < 32; i++) {
        float ai = __shfl_sync(0xffffffffu, a1, i);
        float2 wv = __half22float2(W[(32 + i) * 32 + lane]);
        acc0 = fmaf(ai, wv.x, acc0);
        acc1 = fmaf(ai, wv.y, acc1);
    }
    atomicAdd(&g_agg[d * 64 + 2 * lane], acc0);
    atomicAdd(&g_agg[d * 64 + 2 * lane + 1], acc1);
}

// ---------------- node update: root-lin + GRU, 4 nodes / 256-thread block ----------------
__global__ void k_node(const float* __restrict__ root_w, const float* __restrict__ conv_b,
                       const float* __restrict__ bih, const float* __restrict__ bhh) {
    __shared__ float s_out[4][64], s_h[4][64], s_m[4][64];
    int t = threadIdx.x;
    int ni = t >> 6, j = t & 63;
    int n = blockIdx.x * 4 + ni;
    float ov = g_out[n * 64 + j];
    float hv = g_h[n * 64 + j];
    s_out[ni][j] = ov;
    s_h[ni][j] = hv;
    __syncthreads();
    float m = fmaf(g_agg[n * 64 + j], g_invdeg[n], conv_b[j]);
#pragma unroll 8
    for (int k = 0; k < 64; k++) m = fmaf(s_out[ni][k], root_w[k * 64 + j], m);
    m = lrelu(m);
    s_m[ni][j] = m;
    __syncthreads();
    float ar = bih[j] + bhh[j];
    float az = bih[64 + j] + bhh[64 + j];
    float ain = bih[128 + j];
    float ahn = bhh[128 + j];
#pragma unroll 4
    for (int k = 0; k < 64; k++) {
        const float* w8 = g_wt8 + (k * 64 + j) * 8;
        float4 wa = *(const float4*)(w8);
        float4 wb = *(const float4*)(w8 + 4);
        float mk = s_m[ni][k];
        float hk = s_h[ni][k];
        ar = fmaf(mk, wa.x, ar); ar = fmaf(hk, wa.w, ar);
        az = fmaf(mk, wa.y, az); az = fmaf(hk, wb.x, az);
        ain = fmaf(mk, wa.z, ain);
        ahn = fmaf(hk, wb.y, ahn);
    }
    float r = sigm(ar);
    float z = sigm(az);
    float ng = tanhf(ain + r * ahn);
    float hn = (1.f - z) * ng + z * hv;
    g_h[n * 64 + j] = hn;
    g_out[n * 64 + j] = hn;
}

// ---------------- stem head: 1 stem / 128-thread block ----------------
__global__ void k_stem(const int* __restrict__ sidx, const float* __restrict__ b1,
                       const float* __restrict__ b2, float* __restrict__ outp) {
    __shared__ float a[64], hid[64];
    int st = blockIdx.x;
    int t = threadIdx.x;
    int n = sidx[st];
    if (t < 64) a[t] = g_out[n * 64 + t];
    __syncthreads();
    if (t < 64) {
        float acc = b1[t];
#pragma unroll 8
        for (int k = 0; k < 64; k++) acc = fmaf(a[k], g_s1T[k * 64 + t], acc);
        hid[t] = lrelu(acc);
    }
    __syncthreads();
    if (t < 105) {
        float acc = b2[t];
#pragma unroll 8
        for (int k = 0; k < 64; k++) acc = fmaf(hid[k], g_s2T[k * 105 + t], acc);
        outp[STEM_OFF + st * 105 + t] = acc;
    }
}

// ---------------- jbond head: warp per flattened row ----------------
__global__ void k_jbond(const int* __restrict__ jidx, const float* __restrict__ b1,
                        const float* __restrict__ j2w, const float* __restrict__ j2b) {
    int gw = (blockIdx.x * blockDim.x + threadIdx.x) >> 5;
    int lane = threadIdx.x & 31;
    if (gw >= NS) return;
    int n = jidx[gw];
    float a0 = g_out[n * 64 + lane];
    float a1 = g_out[n * 64 + 32 + lane];
    float h0 = b1[lane], h1 = b1[32 + lane];
#pragma unroll
    for (int i = 0; i < 32; i++) {
        float ai = __shfl_sync(0xffffffffu, a0, i);
        h0 = fmaf(ai, g_j1T[i * 64 + lane], h0);
        h1 = fmaf(ai, g_j1T[i * 64 + 32 + lane], h1);
    }
#pragma unroll
    for (int i = 0; i < 32; i++) {
        float ai = __shfl_sync(0xffffffffu, a1, i);
        h0 = fmaf(ai, g_j1T[(32 + i) * 64 + lane], h0);
        h1 = fmaf(ai, g_j1T[(32 + i) * 64 + 32 + lane], h1);
    }
    float v = lrelu(h0) * j2w[lane] + lrelu(h1) * j2w[32 + lane];
#pragma unroll
    for (int o = 16; o > 0; o >>= 1) v += __shfl_xor_sync(0xffffffffu, v, o);
    if (lane == 0) g_jb[gw] = v + j2b[0];
}

__global__ void k_jmean(float* __restrict__ outp) {
    int i = blockIdx.x * blockDim.x + threadIdx.x;
    if (i >= NJ) return;
    outp[JB_OFF + i] = 0.5f * (g_jb[2 * i] + g_jb[2 * i + 1]);
}

// ---------------- Set2Set (analytic q) ----------------
__global__ void k_qconst(const float* __restrict__ bih, const float* __restrict__ bhh) {
    int j = threadIdx.x;
    if (j >= 64) return;
    float i_ = bih[j] + bhh[j];
    float g_ = bih[128 + j] + bhh[128 + j];
    float o_ = bih[192 + j] + bhh[192 + j];
    float c = sigm(i_) * tanhf(g_);
    g_q[j] = sigm(o_) * tanhf(c);
}

__global__ void k_escore(const int* __restrict__ batch) {
    int gw = (blockIdx.x * blockDim.x + threadIdx.x) >> 5;
    int lane = threadIdx.x & 31;
    if (gw >= NN) return;
    float v = g_out[gw * 64 + lane] * g_q[lane] +
              g_out[gw * 64 + 32 + lane] * g_q[32 + lane];
#pragma unroll
    for (int o = 16; o > 0; o >>= 1) v += __shfl_xor_sync(0xffffffffu, v, o);
    if (lane == 0) {
        g_e[gw] = v;
        atomicMax(&g_emax[batch[gw]], fkey(v));
    }
}

__global__ void k_aun(const int* __restrict__ batch) {
    int n = blockIdx.x * blockDim.x + threadIdx.x;
    if (n >= NN) return;
    int b = batch[n];
    float a = expf(g_e[n] - funkey(g_emax[b]));
    g_aun[n] = a;
    atomicAdd(&g_asum[b], a);
}

__global__ void k_rpool(const int* __restrict__ batch) {
    int idx = blockIdx.x * blockDim.x + threadIdx.x;
    if (idx >= NN * 64) return;
    int n = idx >> 6, j = idx & 63;
    int b = batch[n];
    float w = __fdividef(g_aun[n], g_asum[b]);
    atomicAdd(&g_rpool[b * 64 + j], w * g_out[idx]);
}

__global__ void k_final(const float* __restrict__ lw, const float* __restrict__ lb,
                        float* __restrict__ outp) {
    int t = blockIdx.x * blockDim.x + threadIdx.x;
    if (t >= NG * 2) return;
    int b = t >> 1, o = t & 1;
    float acc = lb[o];
#pragma unroll 8
    for (int j = 0; j < 64; j++) acc = fmaf(g_q[j], lw[o * 128 + j], acc);
#pragma unroll 8
    for (int j = 0; j < 64; j++) acc = fmaf(g_rpool[b * 64 + j], lw[o * 128 + 64 + j], acc);
    outp[t] = acc;
}

// ---------------- launch ----------------
extern "C" void kernel_launch(void* const* d_in, const int* in_sizes, int n_in,
                              void* d_out, int out_size) {
    const float* x        = (const float*)d_in[0];
    const float* ea       = (const float*)d_in[1];
    const float* lin0_w   = (const float*)d_in[2];
    const float* lin0_b   = (const float*)d_in[3];
    const float* en1_w    = (const float*)d_in[4];
    const float* en1_b    = (const float*)d_in[5];
    const float* en2_w    = (const float*)d_in[6];
    const float* en2_b    = (const float*)d_in[7];
    const float* root_w   = (const float*)d_in[8];
    const float* conv_b   = (const float*)d_in[9];
    const float* gru_w_ih = (const float*)d_in[10];
    const float* gru_w_hh = (const float*)d_in[11];
    const float* gru_b_ih = (const float*)d_in[12];
    const float* gru_b_hh = (const float*)d_in[13];
    const float* s1_w     = (const float*)d_in[14];
    const float* s1_b     = (const float*)d_in[15];
    const float* s2_w     = (const float*)d_in[16];
    const float* s2_b     = (const float*)d_in[17];
    const float* j1_w     = (const float*)d_in[18];
    const float* j1_b     = (const float*)d_in[19];
    const float* j2_w     = (const float*)d_in[20];
    const float* j2_b     = (const float*)d_in[21];
    const float* lstm_b_ih = (const float*)d_in[24];
    const float* lstm_b_hh = (const float*)d_in[25];
    const int* edge_index = (const int*)d_in[28];
    const float* lout_w   = (const float*)d_in[26];
    const float* lout_b   = (const float*)d_in[27];
    const int* stem_idx   = (const int*)d_in[29];
    const int* jbond_idx  = (const int*)d_in[30];
    const int* batch      = (const int*)d_in[31];
    float* outp = (float*)d_out;

    void *pDeg, *pAgg, *pEmax, *pAsum, *pRpool;
    cudaGetSymbolAddress(&pDeg, g_deg);
    cudaGetSymbolAddress(&pAgg, g_agg);
    cudaGetSymbolAddress(&pEmax, g_emax);
    cudaGetSymbolAddress(&pAsum, g_asum);
    cudaGetSymbolAddress(&pRpool, g_rpool);

    cudaMemsetAsync(pDeg, 0, NN * sizeof(float));
    cudaMemsetAsync(pEmax, 0, NG * sizeof(unsigned));
    cudaMemsetAsync(pAsum, 0, NG * sizeof(float));
    cudaMemsetAsync(pRpool, 0, NG * 64 * sizeof(float));

    k_lin0<<<(NN * 64 + 255) / 256, 256>>>(x, lin0_w, lin0_b);
    k_h1e<<<(NE * 64 + 255) / 256, 256>>>(ea, en1_w, en1_b);
    k_deg<<<(NE + 255) / 256, 256>>>(edge_index);
    k_invdeg<<<(NN + 255) / 256, 256>>>();
    k_prep_wt8<<<16, 256>>>(gru_w_ih, gru_w_hh);
    k_prep_misc<<<(64 * 105 + 255) / 256, 256>>>(s1_w, s2_w, j1_w);
    k_qconst<<<1, 64>>>(lstm_b_ih, lstm_b_hh);

    dim3 gWe(32, (NE + 127) / 128);
    k_We<<<gWe, 256>>>(en2_w, en2_b);

    for (int it = 0; it < 6; it++) {
        cudaMemsetAsync(pAgg, 0, (size_t)NN * 64 * sizeof(float));
        k_msg<<<(NE * 32 + 255) / 256, 256>>>(edge_index);
        k_node<<<NN / 4, 256>>>(root_w, conv_b, gru_b_ih, gru_b_hh);
    }

    k_stem<<<NS, 128>>>(stem_idx, s1_b, s2_b, outp);
    k_jbond<<<(NS * 32 + 255) / 256, 256>>>(jbond_idx, j1_b, j2_w, j2_b);
    k_jmean<<<(NJ + 255) / 256, 256>>>(outp);

    k_escore<<<(NN * 32 + 255) / 256, 256>>>(batch);
    k_aun<<<(NN + 255) / 256, 256>>>(batch);
    k_rpool<<<(NN * 64 + 255) / 256, 256>>>(batch);
    k_final<<<(NG * 2 + 255) / 256, 256>>>(lout_w, lout_b, outp);
}

// round 16
// speedup vs baseline: 1.7652x; 1.7652x over previous
#include <cuda_runtime.h>
#include <cuda_fp16.h>
#include <math.h>

#define NN 15000
#define NE 30000
#define NE_PAD 30080
#define NG 600
#define NS 6000
#define NJ 3000
#define STEM_OFF 1200
#define JB_OFF 631200

// ---------------- persistent device scratch ----------------
__device__ __half g_We_h[(size_t)NE * 4096]; // [E][64][64] edge weight matrices, fp16 (245.8 MB)
__device__ __half g_h1h[NE_PAD * 64];        // edge hidden, fp16 (padded to 30080 rows)
__device__ __half g_w2h[4096 * 64];          // en2_w in fp16, [j][k]
__device__ float g_out[NN * 64];
__device__ float g_h[NN * 64];
__device__ float g_agg[NN * 64];
__device__ float g_deg[NN];
__device__ float g_invdeg[NN];
__device__ float g_wt8[64 * 64 * 8];         // interleaved transposed GRU weights
__device__ float g_s1T[64 * 64];
__device__ float g_s2T[64 * 105];
__device__ float g_j1T[64 * 64];
__device__ float g_q[64];
__device__ float g_e[NN];
__device__ float g_aun[NN];
__device__ unsigned g_emax[NG];
__device__ float g_asum[NG];
__device__ float g_rpool[NG * 64];
__device__ float g_jb[NS];

__device__ __forceinline__ float lrelu(float v) { return v > 0.f ? v : 0.01f * v; }
__device__ __forceinline__ float sigm(float v) { return 1.f / (1.f + expf(-v)); }
__device__ __forceinline__ unsigned fkey(float f) {
    unsigned u = __float_as_uint(f);
    return (u & 0x80000000u) ? ~u : (u | 0x80000000u);
}
__device__ __forceinline__ float funkey(unsigned k) {
    return (k & 0x80000000u) ? __uint_as_float(k ^ 0x80000000u) : __uint_as_float(~k);
}

__device__ __forceinline__ void mma16816(float& c0, float& c1, float& c2, float& c3,
                                         unsigned a0, unsigned a1, unsigned a2, unsigned a3,
                                         unsigned b0, unsigned b1) {
    asm volatile(
        "mma.sync.aligned.m16n8k16.row.col.f32.f16.f16.f32 "
        "{%0,%1,%2,%3},{%4,%5,%6,%7},{%8,%9},{%0,%1,%2,%3};"
        : "+f"(c0), "+f"(c1), "+f"(c2), "+f"(c3)
        : "r"(a0), "r"(a1), "r"(a2), "r"(a3), "r"(b0), "r"(b1));
}

// ---------------- init: out = h = lrelu(x @ lin0_w^T + b) ----------------
__global__ void k_lin0(const float* __restrict__ x, const float* __restrict__ w,
                       const float* __restrict__ b) {
    int idx = blockIdx.x * blockDim.x + threadIdx.x;
    if (idx >= NN * 64) return;
    int n = idx >> 6, j = idx & 63;
    float acc = b[j];
#pragma unroll
    for (int k = 0; k < 14; k++) acc = fmaf(x[n * 14 + k], w[j * 14 + k], acc);
    float v = lrelu(acc);
    g_out[idx] = v;
    g_h[idx] = v;
}

__global__ void k_deg(const int* __restrict__ ei) {
    int e = blockIdx.x * blockDim.x + threadIdx.x;
    if (e >= NE) return;
    atomicAdd(&g_deg[ei[NE + e]], 1.0f);
}

__global__ void k_invdeg() {
    int n = blockIdx.x * blockDim.x + threadIdx.x;
    if (n >= NN) return;
    g_invdeg[n] = 1.0f / fmaxf(g_deg[n], 1.0f);
}

// ---------------- edge hidden: h1 = lrelu(edge_attr @ en1^T + b) -> fp16 ----------------
__global__ void k_h1e(const float* __restrict__ ea, const float* __restrict__ w,
                      const float* __restrict__ b) {
    int idx = blockIdx.x * blockDim.x + threadIdx.x;
    if (idx >= NE_PAD * 64) return;
    int e = idx >> 6, j = idx & 63;
    float acc = 0.f;
    if (e < NE) {
        acc = b[j];
#pragma unroll
        for (int k = 0; k < 4; k++) acc = fmaf(ea[e * 4 + k], w[j * 4 + k], acc);
        acc = lrelu(acc);
    }
    g_h1h[idx] = __float2half(acc);
}

__global__ void k_prep_w2(const float* __restrict__ w2) {
    int i = blockIdx.x * blockDim.x + threadIdx.x;
    if (i < 4096 * 64) g_w2h[i] = __float2half(w2[i]);
}

// ---------------- We GEMM on tensor cores: [30080,64]f16 @ [64,4096]f16 + bias -> fp16 ----
// block: 128(e) x 128(j), K=64 resident, 8 warps, each warp 64x32 via m16n8k16
__global__ void __launch_bounds__(256) k_We_mma(const float* __restrict__ bias) {
    __shared__ __half As[128 * 72];  // [e][k], stride 72 halfs (bank-conflict-free)
    __shared__ __half Bs[128 * 72];  // [j][k], stride 72
    int t = threadIdx.x;
    int j0 = blockIdx.x * 128;
    int e0 = blockIdx.y * 128;
#pragma unroll
    for (int p = 0; p < 4; p++) {
        int idx = p * 256 + t;
        int r = idx >> 3, seg = idx & 7;
        uint4 v = *(const uint4*)(g_h1h + (size_t)(e0 + r) * 64 + seg * 8);
        *(uint4*)(As + r * 72 + seg * 8) = v;
    }
#pragma unroll
    for (int p = 0; p < 4; p++) {
        int idx = p * 256 + t;
        int r = idx >> 3, seg = idx & 7;
        uint4 v = *(const uint4*)(g_w2h + (size_t)(j0 + r) * 64 + seg * 8);
        *(uint4*)(Bs + r * 72 + seg * 8) = v;
    }
    __syncthreads();
    int wid = t >> 5, lane = t & 31;
    int mW = (wid & 1) * 64, nW = (wid >> 1) * 32;
    int grp = lane >> 2, tg = lane & 3;
    float c[4][4][4];
#pragma unroll
    for (int mt = 0; mt < 4; mt++)
#pragma unroll
        for (int nt = 0; nt < 4; nt++)
#pragma unroll
            for (int q = 0; q < 4; q++) c[mt][nt][q] = 0.f;

#pragma unroll
    for (int kk = 0; kk < 64; kk += 16) {
        unsigned a[4][4], b[4][2];
#pragma unroll
        for (int mt = 0; mt < 4; mt++) {
            const __half* base = As + (mW + mt * 16 + grp) * 72 + kk + tg * 2;
            a[mt][0] = *(const unsigned*)(base);
            a[mt][1] = *(const unsigned*)(base + 8 * 72);
            a[mt][2] = *(const unsigned*)(base + 8);
            a[mt][3] = *(const unsigned*)(base + 8 * 72 + 8);
        }
#pragma unroll
        for (int nt = 0; nt < 4; nt++) {
            const __half* nb = Bs + (nW + nt * 8 + grp) * 72 + kk + tg * 2;
            b[nt][0] = *(const unsigned*)(nb);
            b[nt][1] = *(const unsigned*)(nb + 8);
        }
#pragma unroll
        for (int mt = 0; mt < 4; mt++)
#pragma unroll
            for (int nt = 0; nt < 4; nt++)
                mma16816(c[mt][nt][0], c[mt][nt][1], c[mt][nt][2], c[mt][nt][3],
                         a[mt][0], a[mt][1], a[mt][2], a[mt][3], b[nt][0], b[nt][1]);
    }
    // epilogue: add bias, convert to fp16, store
#pragma unroll
    for (int nt = 0; nt < 4; nt++) {
        int j = j0 + nW + nt * 8 + tg * 2;
        float2 bj = *(const float2*)(bias + j);
#pragma unroll
        for (int mt = 0; mt < 4; mt++) {
            int m0 = e0 + mW + mt * 16 + grp;
            if (m0 < NE) {
                __half2 hv = __floats2half2_rn(c[mt][nt][0] + bj.x, c[mt][nt][1] + bj.y);
                *(__half2*)(g_We_h + (size_t)m0 * 4096 + j) = hv;
            }
            if (m0 + 8 < NE) {
                __half2 hv = __floats2half2_rn(c[mt][nt][2] + bj.x, c[mt][nt][3] + bj.y);
                *(__half2*)(g_We_h + (size_t)(m0 + 8) * 4096 + j) = hv;
            }
        }
    }
}

// ---------------- weight preprocessing ----------------
__global__ void k_prep_wt8(const float* __restrict__ wih, const float* __restrict__ whh) {
    int idx = blockIdx.x * blockDim.x + threadIdx.x;
    if (idx >= 64 * 64) return;
    int k = idx >> 6, j = idx & 63;
    float* w8 = g_wt8 + idx * 8;
    w8[0] = wih[j * 64 + k];
    w8[1] = wih[(64 + j) * 64 + k];
    w8[2] = wih[(128 + j) * 64 + k];
    w8[3] = whh[j * 64 + k];
    w8[4] = whh[(64 + j) * 64 + k];
    w8[5] = whh[(128 + j) * 64 + k];
    w8[6] = 0.f;
    w8[7] = 0.f;
}

__global__ void k_prep_misc(const float* __restrict__ s1w, const float* __restrict__ s2w,
                            const float* __restrict__ j1w) {
    int idx = blockIdx.x * blockDim.x + threadIdx.x;
    if (idx < 64 * 64) {
        int k = idx >> 6, j = idx & 63;
        g_s1T[idx] = s1w[j * 64 + k];
        g_j1T[idx] = j1w[j * 64 + k];
    }
    if (idx < 64 * 105) {
        int j = idx / 105, p = idx % 105;
        g_s2T[idx] = s2w[p * 64 + j];
    }
}

// ---------------- message: warp per edge, fp16 We stream, scatter to agg ----------------
__global__ void k_msg(const int* __restrict__ ei) {
    int gw = (blockIdx.x * blockDim.x + threadIdx.x) >> 5;
    int lane = threadIdx.x & 31;
    if (gw >= NE) return;
    int s = ei[gw];
    int d = ei[NE + gw];
    float a0 = g_out[s * 64 + lane];
    float a1 = g_out[s * 64 + 32 + lane];
    const __half2* W = (const __half2*)(g_We_h + (size_t)gw * 4096);
    float acc0 = 0.f, acc1 = 0.f;
#pragma unroll
    for (int i = 0; i < 32; i++) {
        float ai = __shfl_sync(0xffffffffu, a0, i);
        float2 wv = __half22float2(W[i * 32 + lane]);
        acc0 = fmaf(ai, wv.x, acc0);
        acc1 = fmaf(ai, wv.y, acc1);
    }
#pragma unroll
    for (int i = 0; i < 32; i++) {
        float ai = __shfl_sync(0xffffffffu, a1, i);
        float2 wv = __half22float2(W[(32 + i) * 32 + lane]);
        acc0 = fmaf(ai, wv.x, acc0);
        acc1 = fmaf(ai, wv.y, acc1);
    }
    atomicAdd(&g_agg[d * 64 + 2 * lane], acc0);
    atomicAdd(&g_agg[d * 64 + 2 * lane + 1], acc1);
}

// ---------------- node update: root-lin + GRU, 16 nodes / block, 4 nodes / thread ------
__global__ void __launch_bounds__(256) k_node(const float* __restrict__ root_w,
                                              const float* __restrict__ conv_b,
                                              const float* __restrict__ bih,
                                              const float* __restrict__ bhh) {
    __shared__ float s_out[16][64], s_h[16][64], s_m[16][64];
    int t = threadIdx.x;
    int j = t & 63, g = t >> 6;
    int nb = blockIdx.x * 16;
    float hv[4];
#pragma unroll
    for (int p = 0; p < 4; p++) {
        int ni = g * 4 + p;
        int n = nb + ni;
        float ov = 0.f, hh = 0.f;
        if (n < NN) { ov = g_out[n * 64 + j]; hh = g_h[n * 64 + j]; }
        s_out[ni][j] = ov;
        s_h[ni][j] = hh;
        hv[p] = hh;
    }
    __syncthreads();
    float m[4];
    float cb = conv_b[j];
#pragma unroll
    for (int p = 0; p < 4; p++) {
        int n = nb + g * 4 + p;
        float agg = 0.f, invd = 0.f;
        if (n < NN) {
            agg = g_agg[n * 64 + j];
            invd = g_invdeg[n];
            g_agg[n * 64 + j] = 0.f;  // zero for next iteration (fused memset)
        }
        m[p] = fmaf(agg, invd, cb);
    }
#pragma unroll 8
    for (int k = 0; k < 64; k++) {
        float rw = root_w[k * 64 + j];
#pragma unroll
        for (int p = 0; p < 4; p++) m[p] = fmaf(s_out[g * 4 + p][k], rw, m[p]);
    }
#pragma unroll
    for (int p = 0; p < 4; p++) {
        m[p] = lrelu(m[p]);
        s_m[g * 4 + p][j] = m[p];
    }
    __syncthreads();
    float br = bih[j] + bhh[j];
    float bz = bih[64 + j] + bhh[64 + j];
    float bin = bih[128 + j];
    float bhn = bhh[128 + j];
    float ar[4], az[4], ain[4], ahn[4];
#pragma unroll
    for (int p = 0; p < 4; p++) { ar[p] = br; az[p] = bz; ain[p] = bin; ahn[p] = bhn; }
#pragma unroll 4
    for (int k = 0; k < 64; k++) {
        const float* w8 = g_wt8 + (k * 64 + j) * 8;
        float4 wa = *(const float4*)(w8);
        float4 wb = *(const float4*)(w8 + 4);
#pragma unroll
        for (int p = 0; p < 4; p++) {
            float mk = s_m[g * 4 + p][k];
            float hk = s_h[g * 4 + p][k];
            ar[p] = fmaf(mk, wa.x, ar[p]); ar[p] = fmaf(hk, wa.w, ar[p]);
            az[p] = fmaf(mk, wa.y, az[p]); az[p] = fmaf(hk, wb.x, az[p]);
            ain[p] = fmaf(mk, wa.z, ain[p]);
            ahn[p] = fmaf(hk, wb.y, ahn[p]);
        }
    }
#pragma unroll
    for (int p = 0; p < 4; p++) {
        int n = nb + g * 4 + p;
        if (n >= NN) continue;
        float r = sigm(ar[p]);
        float z = sigm(az[p]);
        float ng = tanhf(ain[p] + r * ahn[p]);
        float hn = (1.f - z) * ng + z * hv[p];
        g_h[n * 64 + j] = hn;
        g_out[n * 64 + j] = hn;
    }
}

// ---------------- stem head: 1 stem / 128-thread block ----------------
__global__ void k_stem(const int* __restrict__ sidx, const float* __restrict__ b1,
                       const float* __restrict__ b2, float* __restrict__ outp) {
    __shared__ float a[64], hid[64];
    int st = blockIdx.x;
    int t = threadIdx.x;
    int n = sidx[st];
    if (t < 64) a[t] = g_out[n * 64 + t];
    __syncthreads();
    if (t < 64) {
        float acc = b1[t];
#pragma unroll 8
        for (int k = 0; k < 64; k++) acc = fmaf(a[k], g_s1T[k * 64 + t], acc);
        hid[t] = lrelu(acc);
    }
    __syncthreads();
    if (t < 105) {
        float acc = b2[t];
#pragma unroll 8
        for (int k = 0; k < 64; k++) acc = fmaf(hid[k], g_s2T[k * 105 + t], acc);
        outp[STEM_OFF + st * 105 + t] = acc;
    }
}

// ---------------- jbond head: warp per flattened row ----------------
__global__ void k_jbond(const int* __restrict__ jidx, const float* __restrict__ b1,
                        const float* __restrict__ j2w, const float* __restrict__ j2b) {
    int gw = (blockIdx.x * blockDim.x + threadIdx.x) >> 5;
    int lane = threadIdx.x & 31;
    if (gw >= NS) return;
    int n = jidx[gw];
    float a0 = g_out[n * 64 + lane];
    float a1 = g_out[n * 64 + 32 + lane];
    float h0 = b1[lane], h1 = b1[32 + lane];
#pragma unroll
    for (int i = 0; i < 32; i++) {
        float ai = __shfl_sync(0xffffffffu, a0, i);
        h0 = fmaf(ai, g_j1T[i * 64 + lane], h0);
        h1 = fmaf(ai, g_j1T[i * 64 + 32 + lane], h1);
    }
#pragma unroll
    for (int i = 0; i < 32; i++) {
        float ai = __shfl_sync(0xffffffffu, a1, i);
        h0 = fmaf(ai, g_j1T[(32 + i) * 64 + lane], h0);
        h1 = fmaf(ai, g_j1T[(32 + i) * 64 + 32 + lane], h1);
    }
    float v = lrelu(h0) * j2w[lane] + lrelu(h1) * j2w[32 + lane];
#pragma unroll
    for (int o = 16; o > 0; o >>= 1) v += __shfl_xor_sync(0xffffffffu, v, o);
    if (lane == 0) g_jb[gw] = v + j2b[0];
}

__global__ void k_jmean(float* __restrict__ outp) {
    int i = blockIdx.x * blockDim.x + threadIdx.x;
    if (i >= NJ) return;
    outp[JB_OFF + i] = 0.5f * (g_jb[2 * i] + g_jb[2 * i + 1]);
}

// ---------------- Set2Set (analytic q) ----------------
__global__ void k_qconst(const float* __restrict__ bih, const float* __restrict__ bhh) {
    int j = threadIdx.x;
    if (j >= 64) return;
    float i_ = bih[j] + bhh[j];
    float g_ = bih[128 + j] + bhh[128 + j];
    float o_ = bih[192 + j] + bhh[192 + j];
    float c = sigm(i_) * tanhf(g_);
    g_q[j] = sigm(o_) * tanhf(c);
}

__global__ void k_escore(const int* __restrict__ batch) {
    int gw = (blockIdx.x * blockDim.x + threadIdx.x) >> 5;
    int lane = threadIdx.x & 31;
    if (gw >= NN) return;
    float v = g_out[gw * 64 + lane] * g_q[lane] +
              g_out[gw * 64 + 32 + lane] * g_q[32 + lane];
#pragma unroll
    for (int o = 16; o > 0; o >>= 1) v += __shfl_xor_sync(0xffffffffu, v, o);
    if (lane == 0) {
        g_e[gw] = v;
        atomicMax(&g_emax[batch[gw]], fkey(v));
    }
}

__global__ void k_aun(const int* __restrict__ batch) {
    int n = blockIdx.x * blockDim.x + threadIdx.x;
    if (n >= NN) return;
    int b = batch[n];
    float a = expf(g_e[n] - funkey(g_emax[b]));
    g_aun[n] = a;
    atomicAdd(&g_asum[b], a);
}

__global__ void k_rpool(const int* __restrict__ batch) {
    int idx = blockIdx.x * blockDim.x + threadIdx.x;
    if (idx >= NN * 64) return;
    int n = idx >> 6, j = idx & 63;
    int b = batch[n];
    float w = __fdividef(g_aun[n], g_asum[b]);
    atomicAdd(&g_rpool[b * 64 + j], w * g_out[idx]);
}

__global__ void k_final(const float* __restrict__ lw, const float* __restrict__ lb,
                        float* __restrict__ outp) {
    int t = blockIdx.x * blockDim.x + threadIdx.x;
    if (t >= NG * 2) return;
    int b = t >> 1, o = t & 1;
    float acc = lb[o];
#pragma unroll 8
    for (int j = 0; j < 64; j++) acc = fmaf(g_q[j], lw[o * 128 + j], acc);
#pragma unroll 8
    for (int j = 0; j < 64; j++) acc = fmaf(g_rpool[b * 64 + j], lw[o * 128 + 64 + j], acc);
    outp[t] = acc;
}

// ---------------- launch ----------------
extern "C" void kernel_launch(void* const* d_in, const int* in_sizes, int n_in,
                              void* d_out, int out_size) {
    const float* x        = (const float*)d_in[0];
    const float* ea       = (const float*)d_in[1];
    const float* lin0_w   = (const float*)d_in[2];
    const float* lin0_b   = (const float*)d_in[3];
    const float* en1_w    = (const float*)d_in[4];
    const float* en1_b    = (const float*)d_in[5];
    const float* en2_w    = (const float*)d_in[6];
    const float* en2_b    = (const float*)d_in[7];
    const float* root_w   = (const float*)d_in[8];
    const float* conv_b   = (const float*)d_in[9];
    const float* gru_w_ih = (const float*)d_in[10];
    const float* gru_w_hh = (const float*)d_in[11];
    const float* gru_b_ih = (const float*)d_in[12];
    const float* gru_b_hh = (const float*)d_in[13];
    const float* s1_w     = (const float*)d_in[14];
    const float* s1_b     = (const float*)d_in[15];
    const float* s2_w     = (const float*)d_in[16];
    const float* s2_b     = (const float*)d_in[17];
    const float* j1_w     = (const float*)d_in[18];
    const float* j1_b     = (const float*)d_in[19];
    const float* j2_w     = (const float*)d_in[20];
    const float* j2_b     = (const float*)d_in[21];
    const float* lstm_b_ih = (const float*)d_in[24];
    const float* lstm_b_hh = (const float*)d_in[25];
    const float* lout_w   = (const float*)d_in[26];
    const float* lout_b   = (const float*)d_in[27];
    const int* edge_index = (const int*)d_in[28];
    const int* stem_idx   = (const int*)d_in[29];
    const int* jbond_idx  = (const int*)d_in[30];
    const int* batch      = (const int*)d_in[31];
    float* outp = (float*)d_out;

    void *pDeg, *pAgg, *pEmax, *pAsum, *pRpool;
    cudaGetSymbolAddress(&pDeg, g_deg);
    cudaGetSymbolAddress(&pAgg, g_agg);
    cudaGetSymbolAddress(&pEmax, g_emax);
    cudaGetSymbolAddress(&pAsum, g_asum);
    cudaGetSymbolAddress(&pRpool, g_rpool);

    cudaMemsetAsync(pDeg, 0, NN * sizeof(float));
    cudaMemsetAsync(pEmax, 0, NG * sizeof(unsigned));
    cudaMemsetAsync(pAsum, 0, NG * sizeof(float));
    cudaMemsetAsync(pRpool, 0, NG * 64 * sizeof(float));
    cudaMemsetAsync(pAgg, 0, (size_t)NN * 64 * sizeof(float));  // once; k_node re-zeroes

    k_lin0<<<(NN * 64 + 255) / 256, 256>>>(x, lin0_w, lin0_b);
    k_h1e<<<(NE_PAD * 64 + 255) / 256, 256>>>(ea, en1_w, en1_b);
    k_prep_w2<<<(4096 * 64 + 255) / 256, 256>>>(en2_w);
    k_deg<<<(NE + 255) / 256, 256>>>(edge_index);
    k_invdeg<<<(NN + 255) / 256, 256>>>();
    k_prep_wt8<<<16, 256>>>(gru_w_ih, gru_w_hh);
    k_prep_misc<<<(64 * 105 + 255) / 256, 256>>>(s1_w, s2_w, j1_w);
    k_qconst<<<1, 64>>>(lstm_b_ih, lstm_b_hh);

    dim3 gWe(32, NE_PAD / 128);  // 32 x 235
    k_We_mma<<<gWe, 256>>>(en2_b);

    for (int it = 0; it < 6; it++) {
        k_msg<<<(NE * 32 + 255) / 256, 256>>>(edge_index);
        k_node<<<(NN + 15) / 16, 256>>>(root_w, conv_b, gru_b_ih, gru_b_hh);
    }

    k_stem<<<NS, 128>>>(stem_idx, s1_b, s2_b, outp);
    k_jbond<<<(NS * 32 + 255) / 256, 256>>>(jbond_idx, j1_b, j2_w, j2_b);
    k_jmean<<<(NJ + 255) / 256, 256>>>(outp);

    k_escore<<<(NN * 32 + 255) / 256, 256>>>(batch);
    k_aun<<<(NN + 255) / 256, 256>>>(batch);
    k_rpool<<<(NN * 64 + 255) / 256, 256>>>(batch);
    k_final<<<(NG * 2 + 255) / 256, 256>>>(lout_w, lout_b, outp);
}